// round 8
// baseline (speedup 1.0000x reference)
#include <cuda_runtime.h>
#include <cuda_bf16.h>
#include <math.h>
#include <stdint.h>

// Problem constants
#define B_ 64
#define S_ 512
#define H_ 1024
#define K3 3072            // 3*H

// GEMM config
#define BN_ 64             // n-tile per CTA
#define KS 16              // K-split -> grid (16, 16) = 256 CTAs
#define KC (K3 / KS)       // 192 K per CTA
#define NSTG (KC / 16)     // 12 k16 stages
#define ASTR 24            // smem A row stride in bf16 (48 B)
#define WSTR 24            // smem W row stride in bf16

// Scratch (__device__ globals; no allocation allowed)
__device__ __align__(16) __nv_bfloat16 g_Ah[B_ * K3];   // feats hi
__device__ __align__(16) __nv_bfloat16 g_Al[B_ * K3];   // feats lo
__device__ __align__(16) float g_part[KS * B_ * H_];    // 4 MB partials

// ---------------------------------------------------------------------------
// helpers
// ---------------------------------------------------------------------------
__device__ __forceinline__ uint32_t smem_u32(const void* p) {
    return (uint32_t)__cvta_generic_to_shared(p);
}
__device__ __forceinline__ void ldmatrix_x4(uint32_t* r, uint32_t addr) {
    asm volatile("ldmatrix.sync.aligned.m8n8.x4.shared.b16 {%0,%1,%2,%3}, [%4];"
                 : "=r"(r[0]), "=r"(r[1]), "=r"(r[2]), "=r"(r[3]) : "r"(addr));
}
__device__ __forceinline__ void mma_bf16(float* c, const uint32_t* a,
                                         uint32_t b0, uint32_t b1) {
    asm volatile(
        "mma.sync.aligned.m16n8k16.row.col.f32.bf16.bf16.f32 "
        "{%0,%1,%2,%3}, {%4,%5,%6,%7}, {%8,%9}, {%0,%1,%2,%3};"
        : "+f"(c[0]), "+f"(c[1]), "+f"(c[2]), "+f"(c[3])
        : "r"(a[0]), "r"(a[1]), "r"(a[2]), "r"(a[3]), "r"(b0), "r"(b1));
}
__device__ __forceinline__ void split_bf16(float x, __nv_bfloat16& h, __nv_bfloat16& l) {
    h = __float2bfloat16_rn(x);
    l = __float2bfloat16_rn(x - __bfloat162float(h));
}

// ---------------------------------------------------------------------------
// Kernel 1: feats -> bf16 hi/lo.
// grid (B, 3, 4): z splits the h-dimension 4-ways so per-block bytes <= 32KB
// and DRAM load spreads evenly across SMs (768 blocks).
// 256 threads = 4 s-slices x 64 h4-slots.  Range length <= 32.
// ---------------------------------------------------------------------------
__global__ __launch_bounds__(256) void feats_kernel(
    const float* __restrict__ hs,
    const int* __restrict__ subj,
    const int* __restrict__ obj)
{
    __shared__ float4 red[3][64];

    const int b   = blockIdx.x;
    const int seg = blockIdx.y;
    const int hz  = blockIdx.z;
    const int tid = threadIdx.x;
    const int HC  = H_ / 4;                  // 256 float4 per row

    const int h4    = hz * 64 + (tid & 63);  // global float4 index in H
    const int slice = tid >> 6;              // 0..3

    const float4* base = (const float4*)(hs + (size_t)b * S_ * H_);

    float4 acc = make_float4(0.f, 0.f, 0.f, 0.f);
    float inv = 1.0f;

    if (seg == 0) {
        if (slice != 0) return;              // whole block is seg0: no sync below
        acc = base[h4];
    } else {
        const int* rng = (seg == 1 ? subj : obj) + b * 2;
        const int s0 = rng[0];
        const int s1 = rng[1];
        const int cnt = s1 - s0;
        inv = 1.0f / (float)(cnt > 0 ? cnt : 1);

        const int sb = s0 + slice;
        #pragma unroll
        for (int i = 0; i < 8; ++i) {        // 4 slices x 8 -> covers len 32
            const int s = sb + i * 4;
            if (s < s1) {
                const float4 v = base[(size_t)s * HC + h4];
                acc.x += v.x; acc.y += v.y; acc.z += v.z; acc.w += v.w;
            }
        }

        if (slice > 0) red[slice - 1][tid & 63] = acc;
        __syncthreads();
        if (slice != 0) return;
        const float4 r0 = red[0][tid & 63];
        const float4 r1 = red[1][tid & 63];
        const float4 r2 = red[2][tid & 63];
        acc.x += r0.x + r1.x + r2.x;
        acc.y += r0.y + r1.y + r2.y;
        acc.z += r0.z + r1.z + r2.z;
        acc.w += r0.w + r1.w + r2.w;
        acc.x *= inv; acc.y *= inv; acc.z *= inv; acc.w *= inv;
    }

    // split to bf16 hi/lo and store
    __nv_bfloat16 h[4], l[4];
    split_bf16(acc.x, h[0], l[0]);
    split_bf16(acc.y, h[1], l[1]);
    split_bf16(acc.z, h[2], l[2]);
    split_bf16(acc.w, h[3], l[3]);

    const size_t off = (size_t)b * K3 + seg * H_ + (size_t)h4 * 4;
    *(__nv_bfloat162*)(g_Ah + off)     = __halves2bfloat162(h[0], h[1]);
    *(__nv_bfloat162*)(g_Ah + off + 2) = __halves2bfloat162(h[2], h[3]);
    *(__nv_bfloat162*)(g_Al + off)     = __halves2bfloat162(l[0], l[1]);
    *(__nv_bfloat162*)(g_Al + off + 2) = __halves2bfloat162(l[2], l[3]);
}

// ---------------------------------------------------------------------------
// Kernel 2: split-bf16 3-term tensor-core GEMM partials.
// grid (16, 16) = 256 CTAs, 256 threads = 8 warps (2m x 4n).
// CTA tile 64m x 64n x 192k.  W [n][k] k-contiguous -> non-trans ldmatrix.
// ONE __syncthreads per stage: ldmatrix(cur) -> store(nxt) -> sync -> mma.
// f32->bf16 split happens at LOAD time (registers), off the sync path.
// ---------------------------------------------------------------------------
struct Stage { uint4 a; uint2 wh; uint2 wl; };

__global__ __launch_bounds__(256) void gemm_partial_kernel(
    const float* __restrict__ Wm)
{
    __shared__ __nv_bfloat16 sAh[2][B_ * ASTR];     // 3 KB x 2
    __shared__ __nv_bfloat16 sAl[2][B_ * ASTR];
    __shared__ __nv_bfloat16 sWh[2][BN_ * WSTR];    // 3 KB x 2
    __shared__ __nv_bfloat16 sWl[2][BN_ * WSTR];

    const int nb   = blockIdx.x;
    const int kb   = blockIdx.y;
    const int tid  = threadIdx.x;
    const int wid  = tid >> 5;
    const int lane = tid & 31;

    const int n0 = nb * BN_;
    const int k0 = kb * KC;

    // A: threads 0-127 load Ah, 128-255 load Al. One uint4 = 8 bf16.
    const int ar = (tid & 127) >> 1;        // row 0..63
    const int ap = tid & 1;                 // k-half of 16
    const __nv_bfloat16* aQ =
        (tid < 128 ? g_Ah : g_Al) + (size_t)ar * K3 + k0 + ap * 8;

    // W: one float4 (4 k) per thread per stage
    const int wrow = tid >> 2;              // 0..63
    const int wk4  = tid & 3;
    const float* wQ = Wm + (size_t)(n0 + wrow) * K3 + k0 + wk4 * 4;

    auto ld_st = [&](int st) {
        Stage q;
        q.a = *(const uint4*)(aQ + st * 16);
        const float4 w = *(const float4*)(wQ + st * 16);
        __nv_bfloat16 h0,h1,h2,h3,l0,l1,l2,l3;
        split_bf16(w.x, h0, l0); split_bf16(w.y, h1, l1);
        split_bf16(w.z, h2, l2); split_bf16(w.w, h3, l3);
        __nv_bfloat162 p;
        p = __halves2bfloat162(h0, h1); q.wh.x = *(uint32_t*)&p;
        p = __halves2bfloat162(h2, h3); q.wh.y = *(uint32_t*)&p;
        p = __halves2bfloat162(l0, l1); q.wl.x = *(uint32_t*)&p;
        p = __halves2bfloat162(l2, l3); q.wl.y = *(uint32_t*)&p;
        return q;
    };
    auto store_stage = [&](int buf, const Stage& q) {
        *(uint4*)((tid < 128 ? sAh[buf] : sAl[buf]) + ar * ASTR + ap * 8) = q.a;
        *(uint2*)(sWh[buf] + wrow * WSTR + wk4 * 4) = q.wh;
        *(uint2*)(sWl[buf] + wrow * WSTR + wk4 * 4) = q.wl;
    };

    // warp compute layout: 2 m-warps x 4 n-warps; warp tile 32m x 16n
    const int mw = wid & 1;
    const int nw = wid >> 1;

    const int a_row = (lane & 15);
    const int a_col = (lane >> 4) << 3;
    const int b_row = (lane & 7) | ((lane >> 4) << 3);
    const int b_col = ((lane >> 3) & 1) << 3;

    float acc[2][2][4];
    #pragma unroll
    for (int i = 0; i < 2; ++i)
        #pragma unroll
        for (int j = 0; j < 2; ++j)
            #pragma unroll
            for (int c = 0; c < 4; ++c) acc[i][j][c] = 0.f;

    // prologue: stage 0 -> smem buf0; stages 1..3 into register ring
    Stage q[3];
    q[0] = ld_st(0);
    store_stage(0, q[0]);
    q[1] = ld_st(1);                        // slot(s) = s % 3
    q[2] = ld_st(2);
    q[0] = ld_st(3);
    __syncthreads();

    #pragma unroll
    for (int t = 0; t < NSTG; ++t) {
        const int cur = t & 1;

        uint32_t ah[2][4], al[2][4], wh[4], wl[4];
        #pragma unroll
        for (int mi = 0; mi < 2; ++mi) {
            const int row = mw * 32 + mi * 16 + a_row;
            ldmatrix_x4(ah[mi], smem_u32(sAh[cur] + row * ASTR + a_col));
            ldmatrix_x4(al[mi], smem_u32(sAl[cur] + row * ASTR + a_col));
        }
        {
            const int row = nw * 16 + b_row;
            ldmatrix_x4(wh, smem_u32(sWh[cur] + row * WSTR + b_col));
            ldmatrix_x4(wl, smem_u32(sWl[cur] + row * WSTR + b_col));
        }

        if (t + 1 < NSTG) {
            store_stage(cur ^ 1, q[(t + 1) % 3]);      // writes buf nxt
            if (t + 4 < NSTG) q[(t + 1) % 3] = ld_st(t + 4);
            __syncthreads();   // orders: reads(cur)@t < writes(cur)@t+1,
                               //         writes(nxt)@t < reads(nxt)@t+1
        }

        #pragma unroll
        for (int mi = 0; mi < 2; ++mi)
            #pragma unroll
            for (int j = 0; j < 2; ++j) {
                const int hf = j * 2;
                mma_bf16(acc[mi][j], ah[mi], wh[hf], wh[hf + 1]); // ah*wh
                mma_bf16(acc[mi][j], ah[mi], wl[hf], wl[hf + 1]); // ah*wl
                mma_bf16(acc[mi][j], al[mi], wh[hf], wh[hf + 1]); // al*wh
            }
    }

    // epilogue: f32 partials
    const int c_row = lane >> 2;
    const int c_col = (lane & 3) * 2;
    float* pbase = g_part + (size_t)kb * (B_ * H_);
    #pragma unroll
    for (int mi = 0; mi < 2; ++mi) {
        #pragma unroll
        for (int j = 0; j < 2; ++j) {
            const int m = mw * 32 + mi * 16 + c_row;
            const int n = n0 + nw * 16 + j * 8 + c_col;
            *(float2*)(pbase + (size_t)m * H_ + n) =
                make_float2(acc[mi][j][0], acc[mi][j][1]);
            *(float2*)(pbase + (size_t)(m + 8) * H_ + n) =
                make_float2(acc[mi][j][2], acc[mi][j][3]);
        }
    }
}

// ---------------------------------------------------------------------------
// Kernel 3: reduce K-split partials + bias + tanh (float4 vectorized)
// grid 128 x 128 threads; each thread one float4 (4 outputs), 16 MLP loads
// ---------------------------------------------------------------------------
__global__ __launch_bounds__(128) void reduce_kernel(
    const float* __restrict__ bias,
    float* __restrict__ out)
{
    const int idx4 = blockIdx.x * 128 + threadIdx.x;  // 0 .. B_*H_/4-1
    const int n4 = idx4 & (H_ / 4 - 1);

    const float4 bv = *(const float4*)(bias + n4 * 4);
    float4 s = bv;
    #pragma unroll
    for (int kb = 0; kb < KS; ++kb) {
        const float4 p = *(const float4*)(g_part + (size_t)kb * (B_ * H_) + idx4 * 4);
        s.x += p.x; s.y += p.y; s.z += p.z; s.w += p.w;
    }

    float4 o;
    o.x = tanhf(s.x); o.y = tanhf(s.y); o.z = tanhf(s.z); o.w = tanhf(s.w);
    *(float4*)(out + idx4 * 4) = o;
}

// ---------------------------------------------------------------------------
extern "C" void kernel_launch(void* const* d_in, const int* in_sizes, int n_in,
                              void* d_out, int out_size)
{
    const float* hs   = (const float*)d_in[0];   // (B, S, H) f32
    const int*   subj = (const int*)  d_in[1];   // (B, 2) i32
    const int*   obj  = (const int*)  d_in[2];   // (B, 2) i32
    const float* Wm   = (const float*)d_in[3];   // (H, 3H) f32
    const float* bias = (const float*)d_in[4];   // (H,) f32
    float*       out  = (float*)d_out;           // (B, H) f32

    (void)in_sizes; (void)n_in; (void)out_size;

    feats_kernel<<<dim3(B_, 3, 4), 256>>>(hs, subj, obj);
    gemm_partial_kernel<<<dim3(H_ / BN_, KS), 256>>>(Wm);
    reduce_kernel<<<(B_ * H_) / 512, 128>>>(bias, out);
}